// round 13
// baseline (speedup 1.0000x reference)
#include <cuda_runtime.h>
#include <cuda_bf16.h>
#include <math.h>
#include <cstdint>

#define L_ 512
#define B_ 64
#define E_ 256
#define H_ 256
#define T_ 12
#define CS 8    // cluster size (verified working)

typedef unsigned long long u64;

// ---------------- helpers ----------------
__device__ __forceinline__ float tanhap(float x) {
    float y;
    asm("tanh.approx.f32 %0, %1;" : "=f"(y) : "f"(x));
    return y;
}
__device__ __forceinline__ float sigap(float x) {
    return fmaf(0.5f, tanhap(0.5f * x), 0.5f);
}
__device__ __forceinline__ float ex2f(float x) {
    float y;
    asm("ex2.approx.f32 %0, %1;" : "=f"(y) : "f"(x));
    return y;
}
__device__ __forceinline__ float lg2f(float x) {
    float y;
    asm("lg2.approx.f32 %0, %1;" : "=f"(y) : "f"(x));
    return y;
}
__device__ __forceinline__ uint32_t smem_u32(const void* p) {
    uint32_t a;
    asm("{ .reg .u64 t; cvta.to.shared.u64 t, %1; cvt.u32.u64 %0, t; }" : "=r"(a) : "l"(p));
    return a;
}
__device__ __forceinline__ uint32_t packbf(float lo, float hi) {
    uint32_t r;
    asm("cvt.rn.bf16x2.f32 %0, %1, %2;" : "=r"(r) : "f"(hi), "f"(lo));
    return r;
}
__device__ __forceinline__ void ldsm_x4(uint32_t& r0, uint32_t& r1, uint32_t& r2, uint32_t& r3, uint32_t addr) {
    asm volatile("ldmatrix.sync.aligned.m8n8.x4.shared.b16 {%0,%1,%2,%3}, [%4];"
        : "=r"(r0), "=r"(r1), "=r"(r2), "=r"(r3) : "r"(addr));
}
__device__ __forceinline__ void mma16816(float& d0, float& d1, float& d2, float& d3,
                                         uint32_t a0, uint32_t a1, uint32_t a2, uint32_t a3,
                                         uint32_t b0, uint32_t b1) {
    asm volatile("mma.sync.aligned.m16n8k16.row.col.f32.bf16.bf16.f32 "
        "{%0,%1,%2,%3}, {%4,%5,%6,%7}, {%8,%9}, {%0,%1,%2,%3};"
        : "+f"(d0), "+f"(d1), "+f"(d2), "+f"(d3)
        : "r"(a0), "r"(a1), "r"(a2), "r"(a3), "r"(b0), "r"(b1));
}
__device__ __forceinline__ uint32_t mapa_rank(uint32_t local, uint32_t rank) {
    uint32_t r;
    asm("mapa.shared::cluster.u32 %0, %1, %2;" : "=r"(r) : "r"(local), "r"(rank));
    return r;
}
__device__ __forceinline__ void stsc_v4(uint32_t addr, uint4 v) {
    asm volatile("st.shared::cluster.v4.b32 [%0], {%1,%2,%3,%4};"
        :: "r"(addr), "r"(v.x), "r"(v.y), "r"(v.z), "r"(v.w) : "memory");
}
__device__ __forceinline__ void mbar_arrive_remote(uint32_t remAddr) {
    asm volatile("mbarrier.arrive.release.cluster.shared::cluster.b64 _, [%0];"
                 :: "r"(remAddr) : "memory");
}
__device__ __forceinline__ void mbar_wait_cluster(uint32_t mbar, uint32_t parity) {
    uint32_t done = 0;
    while (!done) {
        asm volatile(
            "{\n\t.reg .pred p;\n\t"
            "mbarrier.try_wait.parity.acquire.cluster.shared::cta.b64 p, [%1], %2, 0x989680;\n\t"
            "selp.b32 %0, 1, 0, p;\n\t}"
            : "=r"(done) : "r"(mbar), "r"(parity) : "memory");
    }
}

// ---------------- scratch ----------------
__device__ float g_gx[(size_t)2*L_*1024*B_];          // input gates TRANSPOSED: [2][L][gate-row j][b]
__device__ __nv_bfloat16 g_hb[(size_t)2*L_*B_*H_];    // hidden bf16 (consumed only by k_emit)
__device__ float g_emit[(size_t)L_*B_*T_];
__device__ float g_nll[B_];

// ---------------- input-gate GEMM on HMMA (mma.sync bf16; R12-identical) ----------------
static const int IG_PITCH = 528;
static const int IG_SM_W  = 0;
static const int IG_SM_X  = 256 * IG_PITCH;
static const int IG_SM_TOK = IG_SM_X + 64 * IG_PITCH;
static const int INGATE_SMEM = IG_SM_TOK + 256;

__global__ __launch_bounds__(256, 1) void k_ingate(
    const int* __restrict__ sent, const float* __restrict__ emb,
    const float* __restrict__ Wf, const float* __restrict__ bfv,
    const float* __restrict__ Wb, const float* __restrict__ bbv)
{
    extern __shared__ __align__(1024) char smw[];
    uint32_t smb = smem_u32(smw);
    int* tok = (int*)(smw + IG_SM_TOK);
    int lg = blockIdx.x, jb = blockIdx.y;
    int dir = jb >> 2;
    int jjb = (jb & 3) * 256;
    int tid = threadIdx.x;
    int w = tid >> 5, l = tid & 31;
    const float* W  = dir ? Wb : Wf;
    const float* bv = dir ? bbv : bfv;

    {
        const float4* Wf4 = (const float4*)(W + (size_t)jjb*256);
        #pragma unroll 4
        for (int i = 0; i < 64; i++) {
            int idx = i*256 + tid;
            int r = idx >> 6, c4 = idx & 63;
            float4 v = Wf4[(size_t)r*64 + c4];
            *(uint2*)(smw + IG_SM_W + r*IG_PITCH + c4*8) =
                make_uint2(packbf(v.x, v.y), packbf(v.z, v.w));
        }
    }
    int mb = 32*w;
    int rr0 = mb + (l >> 2);
    float bias[4];
    #pragma unroll
    for (int i = 0; i < 4; i++) bias[i] = bv[jjb + rr0 + 8*i];

    uint32_t aAddr[2];
    #pragma unroll
    for (int mt = 0; mt < 2; mt++)
        aAddr[mt] = smb + IG_SM_W + (uint32_t)((mb + mt*16 + (l & 15))*IG_PITCH + (l >> 4)*16);
    uint32_t xAddr[8];
    {
        int lrow = l & 7, grp = l >> 3;
        #pragma unroll
        for (int nt = 0; nt < 8; nt++)
            xAddr[nt] = smb + IG_SM_X + (uint32_t)((nt*8 + lrow)*IG_PITCH + grp*16);
    }
    int cc2 = (l & 3)*2;

    for (int il = 0; il < 8; il++) {
        int lcur = lg*8 + il;
        __syncthreads();
        if (tid < 64) tok[tid] = sent[tid*L_ + lcur];
        __syncthreads();
        #pragma unroll 4
        for (int i = 0; i < 16; i++) {
            int idx = i*256 + tid;
            int r = idx >> 6, c4 = idx & 63;
            float4 v = ((const float4*)emb)[(size_t)tok[r]*64 + c4];
            *(uint2*)(smw + IG_SM_X + r*IG_PITCH + c4*8) =
                make_uint2(packbf(v.x, v.y), packbf(v.z, v.w));
        }
        __syncthreads();

        float acc[2][8][4];
        #pragma unroll
        for (int mt = 0; mt < 2; mt++)
            #pragma unroll
            for (int nt = 0; nt < 8; nt++)
                #pragma unroll
                for (int k = 0; k < 4; k++) acc[mt][nt][k] = 0.f;

        #pragma unroll 2
        for (int ktp = 0; ktp < 8; ktp++) {
            uint32_t af[2][2][4];
            #pragma unroll
            for (int mt = 0; mt < 2; mt++)
                #pragma unroll
                for (int kk = 0; kk < 2; kk++)
                    ldsm_x4(af[mt][kk][0], af[mt][kk][1], af[mt][kk][2], af[mt][kk][3],
                            aAddr[mt] + (ktp*2 + kk)*32);
            #pragma unroll
            for (int nt = 0; nt < 8; nt++) {
                uint32_t b0, b1, b2, b3;
                ldsm_x4(b0, b1, b2, b3, xAddr[nt] + ktp*64);
                #pragma unroll
                for (int mt = 0; mt < 2; mt++) {
                    mma16816(acc[mt][nt][0], acc[mt][nt][1], acc[mt][nt][2], acc[mt][nt][3],
                             af[mt][0][0], af[mt][0][1], af[mt][0][2], af[mt][0][3], b0, b1);
                    mma16816(acc[mt][nt][0], acc[mt][nt][1], acc[mt][nt][2], acc[mt][nt][3],
                             af[mt][1][0], af[mt][1][1], af[mt][1][2], af[mt][1][3], b2, b3);
                }
            }
        }

        float* outb = g_gx + ((size_t)(dir*L_ + lcur)*1024 + jjb)*64;
        #pragma unroll
        for (int mt = 0; mt < 2; mt++) {
            int ra = mb + mt*16 + (l >> 2);
            int rb = ra + 8;
            float ba = bias[mt*2 + 0];
            float bb2 = bias[mt*2 + 1];
            #pragma unroll
            for (int nt = 0; nt < 8; nt++) {
                *(float2*)(outb + (size_t)ra*64 + nt*8 + cc2) =
                    make_float2(acc[mt][nt][0] + ba, acc[mt][nt][1] + ba);
                *(float2*)(outb + (size_t)rb*64 + nt*8 + cc2) =
                    make_float2(acc[mt][nt][2] + bb2, acc[mt][nt][3] + bb2);
            }
        }
    }
}

// ---------------- persistent LSTM: mma.sync, batch-eighth, DSMEM h push (double-buffered) ----------------
// 128 CTAs = (dir 2) x (batch-eighth 8) x (rank 8). CTA owns hids [32p,32p+32), batches [8be,8be+8).
// Per step: wait -> ldsm B[(s-1)&1] (peers pushed h via DSMEM) -> MMA D[128,8] -> Ps=D+gx -> sync
//           -> act -> warp-pack bf16 -> st.shared::cluster 512B to 8 peers' B[s&1] -> fence -> sync -> arrive.
static const int BS_PITCH_B = 528;                    // bytes per B-tile row (8 rows)
static const int BSZ        = 8 * BS_PITCH_B;         // 4224 per buffer
static const int SM_PS      = 2 * BSZ;                // 8448
static const int PS_PITCH   = 10;
static const int SM_MBAR    = SM_PS + 128*PS_PITCH*4; // 8448 + 5120 = 13568
static const int LSTM_SMEM  = SM_MBAR + 128;

__global__ __launch_bounds__(256, 1) __cluster_dims__(CS, 1, 1)
void k_lstm(const float* __restrict__ Whf, const float* __restrict__ Whb)
{
    extern __shared__ __align__(1024) char sm[];
    float* Ps = (float*)(sm + SM_PS);
    uint32_t smb = smem_u32(sm);
    int d  = blockIdx.x >> 6;             // direction
    int be = (blockIdx.x >> 3) & 7;       // batch eighth
    uint32_t p;
    asm("mov.u32 %0, %%cluster_ctarank;" : "=r"(p));
    int hb = (int)p * 32;
    int tid = threadIdx.x;
    int w = tid >> 5, l = tid & 31;
    const float* W = d ? Whb : Whf;

    // zero both B buffers (B[1] read at s=0), init barriers
    for (int i = tid; i < 2*BSZ/4; i += 256) ((uint32_t*)sm)[i] = 0;
    if (tid == 0) {
        asm volatile("mbarrier.init.shared.b64 [%0], %1;" :: "r"(smb + SM_MBAR),     "r"((uint32_t)CS) : "memory");
        asm volatile("mbarrier.init.shared.b64 [%0], %1;" :: "r"(smb + SM_MBAR + 8), "r"((uint32_t)CS) : "memory");
    }
    __syncthreads();
    asm volatile("barrier.cluster.arrive.aligned;" ::: "memory");
    asm volatile("barrier.cluster.wait.aligned;" ::: "memory");

    // ---- A fragments: warp w -> m-rows [16w,16w+16) ----
    int r0 = 16*w + (l >> 2), r1 = r0 + 8;
    const float* wr0 = W + (size_t)((r0 >> 5)*H_ + hb + (r0 & 31))*H_;
    const float* wr1 = W + (size_t)((r1 >> 5)*H_ + hb + (r1 & 31))*H_;
    uint32_t A0[16], A1[16], A2[16], A3[16];
    {
        int kc0 = (l & 3)*2;
        #pragma unroll
        for (int kt = 0; kt < 16; kt++) {
            int kc = kt*16 + kc0;
            A0[kt] = packbf(wr0[kc],   wr0[kc+1]);
            A1[kt] = packbf(wr1[kc],   wr1[kc+1]);
            A2[kt] = packbf(wr0[kc+8], wr0[kc+9]);
            A3[kt] = packbf(wr1[kc+8], wr1[kc+9]);
        }
    }

    // ldsm lane row base (single n-tile of 8 local batches); relative to B0
    uint32_t rowB = smb + (uint32_t)((l & 7)*BS_PITCH_B + (l >> 3)*16);

    // gx accumulator-layout mapping
    int jg0 = (r0 >> 5)*256 + hb + (r0 & 31);
    int jg1 = (r1 >> 5)*256 + hb + (r1 & 31);
    int cc  = (l & 3)*2;

    // phase-B mapping: thread owns exactly one (hid hl, local batch q=w)
    int hl = tid & 31, q = tid >> 5;
    float cst = 0.f;

    // push mapping: pusher lanes (l%8==0) hold uint4 of hids [hb+l, hb+l+8) for batch q.
    // dest in peer pr: B[s&1] + q*528 + 2*hb + (l>>3)*16
    uint32_t dp[CS];
    {
        uint32_t base_local = smb + (uint32_t)(q*BS_PITCH_B + 2*hb + (l >> 3)*16);
        #pragma unroll
        for (int pr = 0; pr < CS; pr++) dp[pr] = mapa_rank(base_local, (uint32_t)pr);
    }
    uint32_t rem0 = 0, rem1 = 0;
    if (tid < CS) {
        rem0 = mapa_rank(smb + SM_MBAR,     (uint32_t)tid);
        rem1 = mapa_rank(smb + SM_MBAR + 8, (uint32_t)tid);
    }
    const unsigned FULL = 0xffffffffu;

    for (int s = 0; s < L_; s++) {
        int t = d ? (L_-1-s) : s;

        // ---- gx prefetch (independent of h) ----
        float2 gx0, gx1;
        {
            const float* base = g_gx + ((size_t)(d*L_ + t)*1024)*64 + 8*be + cc;
            gx0 = *(const float2*)(base + (size_t)jg0*64);
            gx1 = *(const float2*)(base + (size_t)jg1*64);
        }

        // ---- wait: peers' h already in B[(s-1)&1] via DSMEM ----
        if (s > 0) {
            int sp = s - 1;
            mbar_wait_cluster(smb + SM_MBAR + (sp & 1)*8, (uint32_t)((sp >> 1) & 1));
        }
        uint32_t boff = (uint32_t)(((s & 1) ^ 1) * BSZ);   // read B[(s-1)&1]

        // ---- MMA mainloop: D[128,8], warp covers 16 m x 8 n ----
        float a0 = 0.f, a1 = 0.f, a2 = 0.f, a3 = 0.f;
        #pragma unroll
        for (int ktp = 0; ktp < 8; ktp++) {
            uint32_t b0, b1, b2, b3;
            ldsm_x4(b0, b1, b2, b3, rowB + boff + ktp*64);
            mma16816(a0, a1, a2, a3, A0[2*ktp],   A1[2*ktp],   A2[2*ktp],   A3[2*ktp],   b0, b1);
            mma16816(a0, a1, a2, a3, A0[2*ktp+1], A1[2*ktp+1], A2[2*ktp+1], A3[2*ktp+1], b2, b3);
        }

        // ---- Ps = D + gx (single store) ----
        *(float2*)(Ps + r0*PS_PITCH + cc) = make_float2(a0 + gx0.x, a1 + gx0.y);
        *(float2*)(Ps + r1*PS_PITCH + cc) = make_float2(a2 + gx1.x, a3 + gx1.y);
        __syncthreads();

        // ---- activations, c update ----
        float hout;
        {
            float vi = Ps[(  0 + hl)*PS_PITCH + q];
            float vf = Ps[( 32 + hl)*PS_PITCH + q];
            float vg = Ps[( 64 + hl)*PS_PITCH + q];
            float vo = Ps[( 96 + hl)*PS_PITCH + q];
            float ig = sigap(vi), fg = sigap(vf), gg = tanhap(vg), og = sigap(vo);
            cst = fg*cst + ig*gg;
            hout = og * tanhap(cst);
        }

        // ---- warp-pack 32 bf16 -> uint4 in lanes l%8==0, push to 8 peers ----
        if (s < L_-1) {
            float h1 = __shfl_down_sync(FULL, hout, 1);
            uint32_t v0 = packbf(hout, h1);                    // even lanes: hids (l, l+1)
            uint32_t v1 = __shfl_down_sync(FULL, v0, 2);       // lanes%4==0: hids (l+2, l+3)
            uint32_t v2 = __shfl_down_sync(FULL, v0, 4);       // lanes%8==0: hids (l+4, l+5)
            uint32_t v3 = __shfl_down_sync(FULL, v1, 4);       //             hids (l+6, l+7)
            if ((l & 7) == 0) {
                uint4 pk = make_uint4(v0, v1, v2, v3);
                uint32_t bw = (uint32_t)((s & 1) * BSZ);       // write B[s&1]
                #pragma unroll
                for (int pr = 0; pr < CS; pr++) stsc_v4(dp[pr] + bw, pk);
            }
            asm volatile("fence.acq_rel.cluster;" ::: "memory");
        }
        // off-critical-path global h write for k_emit
        g_hb[(((size_t)d*L_ + t)*B_ + 8*be + q)*H_ + hb + hl] = __float2bfloat16(hout);
        __syncthreads();
        if (tid < CS && s < L_-1) {
            mbar_arrive_remote((s & 1) ? rem1 : rem0);
        }
    }
}

// ---------------- emission GEMM (reads bf16 h; unchanged) ----------------
__global__ __launch_bounds__(768) void k_emit(const float* __restrict__ Wem,
                                              const float* __restrict__ bem)
{
    extern __shared__ float smc[];
    float* Hcat = smc;            // [64][520]
    float* Wsm  = smc + 64*520;   // [12][516]
    int l   = blockIdx.x;
    int tid = threadIdx.x;
    const uint4* hf  = (const uint4*)(g_hb + ((size_t)0*L_ + l)*B_*H_);
    const uint4* hbk = (const uint4*)(g_hb + ((size_t)1*L_ + l)*B_*H_);
    for (int e = tid; e < 2048; e += 768) {
        int r = e >> 5, kq = e & 31;
        uint4 vf = hf[e], vb = hbk[e];
        const __nv_bfloat162* pf = (const __nv_bfloat162*)&vf;
        const __nv_bfloat162* pb = (const __nv_bfloat162*)&vb;
        float* df = Hcat + r*520 + kq*8;
        float* db = Hcat + r*520 + 256 + kq*8;
        #pragma unroll
        for (int qq = 0; qq < 4; qq++) {
            float2 f2 = __bfloat1622float2(pf[qq]);
            float2 b2 = __bfloat1622float2(pb[qq]);
            df[2*qq] = f2.x; df[2*qq+1] = f2.y;
            db[2*qq] = b2.x; db[2*qq+1] = b2.y;
        }
    }
    for (int e = tid; e < 12*512; e += 768)
        Wsm[(e >> 9)*516 + (e & 511)] = Wem[e];
    __syncthreads();

    int b = tid / 12, tg = tid - b*12;
    float acc = bem[tg];
    const float4* hrow = (const float4*)(Hcat + b*520);
    const float4* wrow = (const float4*)(Wsm + tg*516);
    #pragma unroll 8
    for (int k4 = 0; k4 < 128; k4++) {
        float4 x = hrow[k4]; float4 w = wrow[k4];
        acc += w.x*x.x + w.y*x.y + w.z*x.z + w.w*x.w;
    }
    g_emit[((size_t)l*B_ + b)*T_ + tg] = acc;
}

// ---------------- CRF NLL: emissions staged in smem, base-2 scan (unchanged) ----------------
__global__ void k_crf(const int* __restrict__ tags, const float* __restrict__ trans)
{
    __shared__ float se[512*12];
    __shared__ float tr[T_*T_];
    int b = blockIdx.x;
    int lane = threadIdx.x;
    for (int i = lane; i < T_*T_; i += 32) tr[i] = trans[i];
    {
        const float4* src = (const float4*)g_emit;
        float4* dst = (float4*)se;
        for (int i = lane; i < 1536; i += 32) {
            int l = i / 3, j = i - 3*l;
            dst[i] = src[((size_t)l*64 + b)*3 + j];
        }
    }
    __syncwarp();

    const unsigned FULL = 0xffffffffu;
    const float I2 = 1.4426950408889634f;
    const float LN2 = 0.6931471805599453f;
    int mylane = (lane < T_) ? lane : 0;
    float trr2[T_];
    #pragma unroll
    for (int t2 = 0; t2 < T_; t2++) trr2[t2] = tr[t2*T_ + mylane] * I2;

    float a2 = se[mylane] * I2;
    #pragma unroll 4
    for (int l = 1; l < L_; l++) {
        float e2 = se[l*12 + mylane] * I2;
        float v[T_];
        #pragma unroll
        for (int t2 = 0; t2 < T_; t2++)
            v[t2] = __shfl_sync(FULL, a2, t2) + trr2[t2];
        float ex[T_];
        ex[0] = 1.0f;
        #pragma unroll
        for (int t2 = 1; t2 < T_; t2++) ex[t2] = ex2f(v[t2] - v[0]);
        float s01 = ex[0] + ex[1],  s23 = ex[2] + ex[3];
        float s45 = ex[4] + ex[5],  s67 = ex[6] + ex[7];
        float s89 = ex[8] + ex[9],  sAB = ex[10] + ex[11];
        float ssum = ((s01 + s23) + (s45 + s67)) + (s89 + sAB);
        a2 = v[0] + lg2f(ssum) + e2;
    }
    float am = (lane < T_) ? a2 : -1e30f;
    float mm = am;
    for (int o = 16; o; o >>= 1) mm = fmaxf(mm, __shfl_xor_sync(FULL, mm, o));
    float es = (lane < T_) ? ex2f(a2 - mm) : 0.f;
    for (int o = 16; o; o >>= 1) es += __shfl_xor_sync(FULL, es, o);
    float logZ = (mm + lg2f(es)) * LN2;

    float eg = 0.f, tg2 = 0.f;
    for (int l = lane; l < L_; l += 32) {
        int tv = tags[b*L_ + l];
        eg += se[l*12 + tv];
    }
    for (int l = lane; l < L_-1; l += 32) {
        int t0v = tags[b*L_ + l], t1v = tags[b*L_ + l + 1];
        tg2 += tr[t0v*T_ + t1v];
    }
    for (int o = 16; o; o >>= 1) {
        eg  += __shfl_xor_sync(FULL, eg,  o);
        tg2 += __shfl_xor_sync(FULL, tg2, o);
    }
    if (lane == 0) g_nll[b] = logZ - eg - tg2;
}

__global__ void k_mean(float* out)
{
    int lane = threadIdx.x;
    float s = (lane < 32) ? g_nll[lane] + g_nll[lane + 32] : 0.f;
    s += __shfl_xor_sync(0xffffffffu, s, 16);
    s += __shfl_xor_sync(0xffffffffu, s, 8);
    s += __shfl_xor_sync(0xffffffffu, s, 4);
    s += __shfl_xor_sync(0xffffffffu, s, 2);
    s += __shfl_xor_sync(0xffffffffu, s, 1);
    if (lane == 0) out[0] = s / (float)B_;
}

// ---------------- launch ----------------
extern "C" void kernel_launch(void* const* d_in, const int* in_sizes, int n_in,
                              void* d_out, int out_size)
{
    const int*   sent  = (const int*)  d_in[0];
    const int*   tags  = (const int*)  d_in[1];
    const float* emb   = (const float*)d_in[2];
    const float* Wihf  = (const float*)d_in[3];
    const float* Whhf  = (const float*)d_in[4];
    const float* bf    = (const float*)d_in[5];
    const float* Wihb  = (const float*)d_in[6];
    const float* Whhb  = (const float*)d_in[7];
    const float* bb    = (const float*)d_in[8];
    const float* Wem   = (const float*)d_in[9];
    const float* bem   = (const float*)d_in[10];
    const float* trans = (const float*)d_in[11];
    float* out = (float*)d_out;

    cudaFuncSetAttribute(k_ingate, cudaFuncAttributeMaxDynamicSharedMemorySize, INGATE_SMEM);
    cudaFuncSetAttribute(k_lstm,   cudaFuncAttributeMaxDynamicSharedMemorySize, LSTM_SMEM);
    cudaFuncSetAttribute(k_emit,   cudaFuncAttributeMaxDynamicSharedMemorySize, (64*520 + 12*516)*4);

    dim3 gA(64, 8);
    k_ingate<<<gA, 256, INGATE_SMEM>>>(sent, emb, Wihf, bf, Wihb, bb);
    k_lstm<<<128, 256, LSTM_SMEM>>>(Whhf, Whhb);
    k_emit<<<L_, 768, (64*520 + 12*516)*4>>>(Wem, bem);
    k_crf<<<B_, 32>>>(tags, trans);
    k_mean<<<1, 32>>>(out);
}

// round 14
// speedup vs baseline: 1.0565x; 1.0565x over previous
#include <cuda_runtime.h>
#include <cuda_bf16.h>
#include <math.h>
#include <cstdint>

#define L_ 512
#define B_ 64
#define E_ 256
#define H_ 256
#define T_ 12
#define CS 8    // cluster size (verified working)

typedef unsigned long long u64;

// ---------------- helpers ----------------
__device__ __forceinline__ float tanhap(float x) {
    float y;
    asm("tanh.approx.f32 %0, %1;" : "=f"(y) : "f"(x));
    return y;
}
__device__ __forceinline__ float sigap(float x) {
    return fmaf(0.5f, tanhap(0.5f * x), 0.5f);
}
__device__ __forceinline__ float ex2f(float x) {
    float y;
    asm("ex2.approx.f32 %0, %1;" : "=f"(y) : "f"(x));
    return y;
}
__device__ __forceinline__ float lg2f(float x) {
    float y;
    asm("lg2.approx.f32 %0, %1;" : "=f"(y) : "f"(x));
    return y;
}
__device__ __forceinline__ uint32_t smem_u32(const void* p) {
    uint32_t a;
    asm("{ .reg .u64 t; cvta.to.shared.u64 t, %1; cvt.u32.u64 %0, t; }" : "=r"(a) : "l"(p));
    return a;
}
__device__ __forceinline__ uint32_t packbf(float lo, float hi) {
    uint32_t r;
    asm("cvt.rn.bf16x2.f32 %0, %1, %2;" : "=r"(r) : "f"(hi), "f"(lo));
    return r;
}
__device__ __forceinline__ void ldsm_x4(uint32_t& r0, uint32_t& r1, uint32_t& r2, uint32_t& r3, uint32_t addr) {
    asm volatile("ldmatrix.sync.aligned.m8n8.x4.shared.b16 {%0,%1,%2,%3}, [%4];"
        : "=r"(r0), "=r"(r1), "=r"(r2), "=r"(r3) : "r"(addr));
}
__device__ __forceinline__ void mma16816(float& d0, float& d1, float& d2, float& d3,
                                         uint32_t a0, uint32_t a1, uint32_t a2, uint32_t a3,
                                         uint32_t b0, uint32_t b1) {
    asm volatile("mma.sync.aligned.m16n8k16.row.col.f32.bf16.bf16.f32 "
        "{%0,%1,%2,%3}, {%4,%5,%6,%7}, {%8,%9}, {%0,%1,%2,%3};"
        : "+f"(d0), "+f"(d1), "+f"(d2), "+f"(d3)
        : "r"(a0), "r"(a1), "r"(a2), "r"(a3), "r"(b0), "r"(b1));
}
__device__ __forceinline__ uint32_t mapa_rank(uint32_t local, uint32_t rank) {
    uint32_t r;
    asm("mapa.shared::cluster.u32 %0, %1, %2;" : "=r"(r) : "r"(local), "r"(rank));
    return r;
}
__device__ __forceinline__ void mbar_arrive_remote(uint32_t remAddr) {
    asm volatile("mbarrier.arrive.release.cluster.shared::cluster.b64 _, [%0];"
                 :: "r"(remAddr) : "memory");
}
__device__ __forceinline__ void mbar_wait_cluster(uint32_t mbar, uint32_t parity) {
    uint32_t done = 0;
    while (!done) {
        asm volatile(
            "{\n\t.reg .pred p;\n\t"
            "mbarrier.try_wait.parity.acquire.cluster.shared::cta.b64 p, [%1], %2, 0x989680;\n\t"
            "selp.b32 %0, 1, 0, p;\n\t}"
            : "=r"(done) : "r"(mbar), "r"(parity) : "memory");
    }
}

// ---------------- scratch ----------------
__device__ float g_gx[(size_t)2*L_*1024*B_];          // input gates TRANSPOSED: [2][L][gate-row j][b]
__device__ __nv_bfloat16 g_hb[(size_t)2*L_*B_*H_];    // hidden bf16
__device__ float g_emit[(size_t)L_*B_*T_];
__device__ float g_nll[B_];

// ---------------- input-gate GEMM on HMMA (mma.sync bf16; R12-identical) ----------------
static const int IG_PITCH = 528;
static const int IG_SM_W  = 0;
static const int IG_SM_X  = 256 * IG_PITCH;
static const int IG_SM_TOK = IG_SM_X + 64 * IG_PITCH;
static const int INGATE_SMEM = IG_SM_TOK + 256;

__global__ __launch_bounds__(256, 1) void k_ingate(
    const int* __restrict__ sent, const float* __restrict__ emb,
    const float* __restrict__ Wf, const float* __restrict__ bfv,
    const float* __restrict__ Wb, const float* __restrict__ bbv)
{
    extern __shared__ __align__(1024) char smw[];
    uint32_t smb = smem_u32(smw);
    int* tok = (int*)(smw + IG_SM_TOK);
    int lg = blockIdx.x, jb = blockIdx.y;
    int dir = jb >> 2;
    int jjb = (jb & 3) * 256;
    int tid = threadIdx.x;
    int w = tid >> 5, l = tid & 31;
    const float* W  = dir ? Wb : Wf;
    const float* bv = dir ? bbv : bfv;

    {
        const float4* Wf4 = (const float4*)(W + (size_t)jjb*256);
        #pragma unroll 4
        for (int i = 0; i < 64; i++) {
            int idx = i*256 + tid;
            int r = idx >> 6, c4 = idx & 63;
            float4 v = Wf4[(size_t)r*64 + c4];
            *(uint2*)(smw + IG_SM_W + r*IG_PITCH + c4*8) =
                make_uint2(packbf(v.x, v.y), packbf(v.z, v.w));
        }
    }
    int mb = 32*w;
    int rr0 = mb + (l >> 2);
    float bias[4];
    #pragma unroll
    for (int i = 0; i < 4; i++) bias[i] = bv[jjb + rr0 + 8*i];

    uint32_t aAddr[2];
    #pragma unroll
    for (int mt = 0; mt < 2; mt++)
        aAddr[mt] = smb + IG_SM_W + (uint32_t)((mb + mt*16 + (l & 15))*IG_PITCH + (l >> 4)*16);
    uint32_t xAddr[8];
    {
        int lrow = l & 7, grp = l >> 3;
        #pragma unroll
        for (int nt = 0; nt < 8; nt++)
            xAddr[nt] = smb + IG_SM_X + (uint32_t)((nt*8 + lrow)*IG_PITCH + grp*16);
    }
    int cc2 = (l & 3)*2;

    for (int il = 0; il < 8; il++) {
        int lcur = lg*8 + il;
        __syncthreads();
        if (tid < 64) tok[tid] = sent[tid*L_ + lcur];
        __syncthreads();
        #pragma unroll 4
        for (int i = 0; i < 16; i++) {
            int idx = i*256 + tid;
            int r = idx >> 6, c4 = idx & 63;
            float4 v = ((const float4*)emb)[(size_t)tok[r]*64 + c4];
            *(uint2*)(smw + IG_SM_X + r*IG_PITCH + c4*8) =
                make_uint2(packbf(v.x, v.y), packbf(v.z, v.w));
        }
        __syncthreads();

        float acc[2][8][4];
        #pragma unroll
        for (int mt = 0; mt < 2; mt++)
            #pragma unroll
            for (int nt = 0; nt < 8; nt++)
                #pragma unroll
                for (int k = 0; k < 4; k++) acc[mt][nt][k] = 0.f;

        #pragma unroll 2
        for (int ktp = 0; ktp < 8; ktp++) {
            uint32_t af[2][2][4];
            #pragma unroll
            for (int mt = 0; mt < 2; mt++)
                #pragma unroll
                for (int kk = 0; kk < 2; kk++)
                    ldsm_x4(af[mt][kk][0], af[mt][kk][1], af[mt][kk][2], af[mt][kk][3],
                            aAddr[mt] + (ktp*2 + kk)*32);
            #pragma unroll
            for (int nt = 0; nt < 8; nt++) {
                uint32_t b0, b1, b2, b3;
                ldsm_x4(b0, b1, b2, b3, xAddr[nt] + ktp*64);
                #pragma unroll
                for (int mt = 0; mt < 2; mt++) {
                    mma16816(acc[mt][nt][0], acc[mt][nt][1], acc[mt][nt][2], acc[mt][nt][3],
                             af[mt][0][0], af[mt][0][1], af[mt][0][2], af[mt][0][3], b0, b1);
                    mma16816(acc[mt][nt][0], acc[mt][nt][1], acc[mt][nt][2], acc[mt][nt][3],
                             af[mt][1][0], af[mt][1][1], af[mt][1][2], af[mt][1][3], b2, b3);
                }
            }
        }

        float* outb = g_gx + ((size_t)(dir*L_ + lcur)*1024 + jjb)*64;
        #pragma unroll
        for (int mt = 0; mt < 2; mt++) {
            int ra = mb + mt*16 + (l >> 2);
            int rb = ra + 8;
            float ba = bias[mt*2 + 0];
            float bb2 = bias[mt*2 + 1];
            #pragma unroll
            for (int nt = 0; nt < 8; nt++) {
                *(float2*)(outb + (size_t)ra*64 + nt*8 + cc2) =
                    make_float2(acc[mt][nt][0] + ba, acc[mt][nt][1] + ba);
                *(float2*)(outb + (size_t)rb*64 + nt*8 + cc2) =
                    make_float2(acc[mt][nt][2] + bb2, acc[mt][nt][3] + bb2);
            }
        }
    }
}

// ---------------- persistent LSTM: mma.sync, L2 h-exchange, batch-eighth (R12 skeleton) ----------------
// 128 CTAs = (dir 2) x (batch-eighth 8) x (rank 8). CTA owns hids [32p,32p+32), batches [8be,8be+8).
// R14: gx double-buffer prefetch + named-barrier arrive/sync split replacing the 3rd __syncthreads.
static const int BS_PITCH_B = 528;                    // bytes per B-tile row (8 rows)
static const int SM_PS      = 8 * BS_PITCH_B;         // 4224 (B tile)
static const int PS_PITCH   = 10;
static const int SM_MBAR    = SM_PS + 128*PS_PITCH*4; // 4224 + 5120 = 9344
static const int LSTM_SMEM  = SM_MBAR + 128;

__global__ __launch_bounds__(256, 1) __cluster_dims__(CS, 1, 1)
void k_lstm(const float* __restrict__ Whf, const float* __restrict__ Whb)
{
    extern __shared__ __align__(1024) char sm[];
    float* Ps = (float*)(sm + SM_PS);
    uint32_t smb = smem_u32(sm);
    int d  = blockIdx.x >> 6;             // direction
    int be = (blockIdx.x >> 3) & 7;       // batch eighth
    uint32_t p;
    asm("mov.u32 %0, %%cluster_ctarank;" : "=r"(p));
    int hb = (int)p * 32;
    int tid = threadIdx.x;
    int w = tid >> 5, l = tid & 31;
    const float* W = d ? Whb : Whf;

    if (tid == 0) {
        asm volatile("mbarrier.init.shared.b64 [%0], %1;" :: "r"(smb + SM_MBAR),     "r"((uint32_t)CS) : "memory");
        asm volatile("mbarrier.init.shared.b64 [%0], %1;" :: "r"(smb + SM_MBAR + 8), "r"((uint32_t)CS) : "memory");
    }
    __syncthreads();
    asm volatile("barrier.cluster.arrive.aligned;" ::: "memory");
    asm volatile("barrier.cluster.wait.aligned;" ::: "memory");

    // ---- A fragments: warp w -> m-rows [16w,16w+16) ----
    int r0 = 16*w + (l >> 2), r1 = r0 + 8;
    const float* wr0 = W + (size_t)((r0 >> 5)*H_ + hb + (r0 & 31))*H_;
    const float* wr1 = W + (size_t)((r1 >> 5)*H_ + hb + (r1 & 31))*H_;
    uint32_t A0[16], A1[16], A2[16], A3[16];
    {
        int kc0 = (l & 3)*2;
        #pragma unroll
        for (int kt = 0; kt < 16; kt++) {
            int kc = kt*16 + kc0;
            A0[kt] = packbf(wr0[kc],   wr0[kc+1]);
            A1[kt] = packbf(wr1[kc],   wr1[kc+1]);
            A2[kt] = packbf(wr0[kc+8], wr0[kc+9]);
            A3[kt] = packbf(wr1[kc+8], wr1[kc+9]);
        }
    }

    // ldsm lane row base (single n-tile of 8 local batches)
    uint32_t rowB = smb + (uint32_t)((l & 7)*BS_PITCH_B + (l >> 3)*16);

    // gx accumulator-layout mapping
    int jg0 = (r0 >> 5)*256 + hb + (r0 & 31);
    int jg1 = (r1 >> 5)*256 + hb + (r1 & 31);
    int cc  = (l & 3)*2;

    // phase-B mapping: thread owns exactly one (hid hl, local batch q)
    int hl = tid & 31, q = tid >> 5;
    float cst = 0.f;

    uint32_t rem0 = 0, rem1 = 0;
    if (tid < CS) {
        rem0 = mapa_rank(smb + SM_MBAR,     (uint32_t)tid);
        rem1 = mapa_rank(smb + SM_MBAR + 8, (uint32_t)tid);
    }

    // ---- gx prefetch for step 0 ----
    float2 gx0, gx1;
    {
        int t0 = d ? (L_-1) : 0;
        const float* base = g_gx + ((size_t)(d*L_ + t0)*1024)*64 + 8*be + cc;
        gx0 = *(const float2*)(base + (size_t)jg0*64);
        gx1 = *(const float2*)(base + (size_t)jg1*64);
    }

    for (int s = 0; s < L_; s++) {
        int t = d ? (L_-1-s) : s;

        // ---- wait + stage h (bf16 copy, this batch eighth: 4 KB) ----
        if (s == 0) {
            for (int i = tid; i < SM_PS/4; i += 256) ((uint32_t*)sm)[i] = 0;
        } else {
            int sp = s - 1;
            mbar_wait_cluster(smb + SM_MBAR + (sp & 1)*8, (uint32_t)((sp >> 1) & 1));
            int tprev = d ? (t+1) : (t-1);
            const uint4* hsrc = (const uint4*)(g_hb + (((size_t)d*L_ + tprev)*B_ + 8*be)*H_);
            int b = tid >> 5, kq = tid & 31;   // 256 uint4, one per thread
            *(uint4*)(sm + b*BS_PITCH_B + kq*16) = hsrc[tid];
        }
        __syncthreads();                               // sync A

        // ---- MMA mainloop: D[128,8], warp covers 16 m x 8 n ----
        float a0 = 0.f, a1 = 0.f, a2 = 0.f, a3 = 0.f;
        #pragma unroll
        for (int ktp = 0; ktp < 8; ktp++) {
            uint32_t b0, b1, b2, b3;
            ldsm_x4(b0, b1, b2, b3, rowB + ktp*64);
            mma16816(a0, a1, a2, a3, A0[2*ktp],   A1[2*ktp],   A2[2*ktp],   A3[2*ktp],   b0, b1);
            mma16816(a0, a1, a2, a3, A0[2*ktp+1], A1[2*ktp+1], A2[2*ktp+1], A3[2*ktp+1], b2, b3);
        }

        // ---- Ps = D + gx (single store) ----
        *(float2*)(Ps + r0*PS_PITCH + cc) = make_float2(a0 + gx0.x, a1 + gx0.y);
        *(float2*)(Ps + r1*PS_PITCH + cc) = make_float2(a2 + gx1.x, a3 + gx1.y);

        // ---- prefetch gx for step s+1 (hidden under act + signal + wait + stage) ----
        if (s + 1 < L_) {
            int tn = d ? (t-1) : (t+1);
            const float* base = g_gx + ((size_t)(d*L_ + tn)*1024)*64 + 8*be + cc;
            gx0 = *(const float2*)(base + (size_t)jg0*64);
            gx1 = *(const float2*)(base + (size_t)jg1*64);
        }
        __syncthreads();                               // sync B

        // ---- phase B: activations, c update, h out (bf16) ----
        float hout;
        {
            float vi = Ps[(  0 + hl)*PS_PITCH + q];
            float vf = Ps[( 32 + hl)*PS_PITCH + q];
            float vg = Ps[( 64 + hl)*PS_PITCH + q];
            float vo = Ps[( 96 + hl)*PS_PITCH + q];
            float ig = sigap(vi), fg = sigap(vf), gg = tanhap(vg), og = sigap(vo);
            cst = fg*cst + ig*gg;
            hout = og * tanhap(cst);
        }
        g_hb[(((size_t)d*L_ + t)*B_ + 8*be + q)*H_ + hb + hl] = __float2bfloat16(hout);

        // ---- signal: warps 1-7 arrive-only (proceed to next wait); warp 0 syncs + releases ----
        if (s < L_-1) {
            if (w != 0) {
                asm volatile("bar.arrive 1, 256;" ::: "memory");
            } else {
                asm volatile("bar.sync 1, 256;" ::: "memory");
                if (tid < CS) mbar_arrive_remote((s & 1) ? rem1 : rem0);
            }
        }
    }
}

// ---------------- emission GEMM (reads bf16 h; unchanged) ----------------
__global__ __launch_bounds__(768) void k_emit(const float* __restrict__ Wem,
                                              const float* __restrict__ bem)
{
    extern __shared__ float smc[];
    float* Hcat = smc;            // [64][520]
    float* Wsm  = smc + 64*520;   // [12][516]
    int l   = blockIdx.x;
    int tid = threadIdx.x;
    const uint4* hf  = (const uint4*)(g_hb + ((size_t)0*L_ + l)*B_*H_);
    const uint4* hbk = (const uint4*)(g_hb + ((size_t)1*L_ + l)*B_*H_);
    for (int e = tid; e < 2048; e += 768) {
        int r = e >> 5, kq = e & 31;
        uint4 vf = hf[e], vb = hbk[e];
        const __nv_bfloat162* pf = (const __nv_bfloat162*)&vf;
        const __nv_bfloat162* pb = (const __nv_bfloat162*)&vb;
        float* df = Hcat + r*520 + kq*8;
        float* db = Hcat + r*520 + 256 + kq*8;
        #pragma unroll
        for (int qq = 0; qq < 4; qq++) {
            float2 f2 = __bfloat1622float2(pf[qq]);
            float2 b2 = __bfloat1622float2(pb[qq]);
            df[2*qq] = f2.x; df[2*qq+1] = f2.y;
            db[2*qq] = b2.x; db[2*qq+1] = b2.y;
        }
    }
    for (int e = tid; e < 12*512; e += 768)
        Wsm[(e >> 9)*516 + (e & 511)] = Wem[e];
    __syncthreads();

    int b = tid / 12, tg = tid - b*12;
    float acc = bem[tg];
    const float4* hrow = (const float4*)(Hcat + b*520);
    const float4* wrow = (const float4*)(Wsm + tg*516);
    #pragma unroll 8
    for (int k4 = 0; k4 < 128; k4++) {
        float4 x = hrow[k4]; float4 w = wrow[k4];
        acc += w.x*x.x + w.y*x.y + w.z*x.z + w.w*x.w;
    }
    g_emit[((size_t)l*B_ + b)*T_ + tg] = acc;
}

// ---------------- CRF NLL: emissions staged in smem, base-2 scan (unchanged) ----------------
__global__ void k_crf(const int* __restrict__ tags, const float* __restrict__ trans)
{
    __shared__ float se[512*12];
    __shared__ float tr[T_*T_];
    int b = blockIdx.x;
    int lane = threadIdx.x;
    for (int i = lane; i < T_*T_; i += 32) tr[i] = trans[i];
    {
        const float4* src = (const float4*)g_emit;
        float4* dst = (float4*)se;
        for (int i = lane; i < 1536; i += 32) {
            int l = i / 3, j = i - 3*l;
            dst[i] = src[((size_t)l*64 + b)*3 + j];
        }
    }
    __syncwarp();

    const unsigned FULL = 0xffffffffu;
    const float I2 = 1.4426950408889634f;
    const float LN2 = 0.6931471805599453f;
    int mylane = (lane < T_) ? lane : 0;
    float trr2[T_];
    #pragma unroll
    for (int t2 = 0; t2 < T_; t2++) trr2[t2] = tr[t2*T_ + mylane] * I2;

    float a2 = se[mylane] * I2;
    #pragma unroll 4
    for (int l = 1; l < L_; l++) {
        float e2 = se[l*12 + mylane] * I2;
        float v[T_];
        #pragma unroll
        for (int t2 = 0; t2 < T_; t2++)
            v[t2] = __shfl_sync(FULL, a2, t2) + trr2[t2];
        float ex[T_];
        ex[0] = 1.0f;
        #pragma unroll
        for (int t2 = 1; t2 < T_; t2++) ex[t2] = ex2f(v[t2] - v[0]);
        float s01 = ex[0] + ex[1],  s23 = ex[2] + ex[3];
        float s45 = ex[4] + ex[5],  s67 = ex[6] + ex[7];
        float s89 = ex[8] + ex[9],  sAB = ex[10] + ex[11];
        float ssum = ((s01 + s23) + (s45 + s67)) + (s89 + sAB);
        a2 = v[0] + lg2f(ssum) + e2;
    }
    float am = (lane < T_) ? a2 : -1e30f;
    float mm = am;
    for (int o = 16; o; o >>= 1) mm = fmaxf(mm, __shfl_xor_sync(FULL, mm, o));
    float es = (lane < T_) ? ex2f(a2 - mm) : 0.f;
    for (int o = 16; o; o >>= 1) es += __shfl_xor_sync(FULL, es, o);
    float logZ = (mm + lg2f(es)) * LN2;

    float eg = 0.f, tg2 = 0.f;
    for (int l = lane; l < L_; l += 32) {
        int tv = tags[b*L_ + l];
        eg += se[l*12 + tv];
    }
    for (int l = lane; l < L_-1; l += 32) {
        int t0v = tags[b*L_ + l], t1v = tags[b*L_ + l + 1];
        tg2 += tr[t0v*T_ + t1v];
    }
    for (int o = 16; o; o >>= 1) {
        eg  += __shfl_xor_sync(FULL, eg,  o);
        tg2 += __shfl_xor_sync(FULL, tg2, o);
    }
    if (lane == 0) g_nll[b] = logZ - eg - tg2;
}

__global__ void k_mean(float* out)
{
    int lane = threadIdx.x;
    float s = (lane < 32) ? g_nll[lane] + g_nll[lane + 32] : 0.f;
    s += __shfl_xor_sync(0xffffffffu, s, 16);
    s += __shfl_xor_sync(0xffffffffu, s, 8);
    s += __shfl_xor_sync(0xffffffffu, s, 4);
    s += __shfl_xor_sync(0xffffffffu, s, 2);
    s += __shfl_xor_sync(0xffffffffu, s, 1);
    if (lane == 0) out[0] = s / (float)B_;
}

// ---------------- launch ----------------
extern "C" void kernel_launch(void* const* d_in, const int* in_sizes, int n_in,
                              void* d_out, int out_size)
{
    const int*   sent  = (const int*)  d_in[0];
    const int*   tags  = (const int*)  d_in[1];
    const float* emb   = (const float*)d_in[2];
    const float* Wihf  = (const float*)d_in[3];
    const float* Whhf  = (const float*)d_in[4];
    const float* bf    = (const float*)d_in[5];
    const float* Wihb  = (const float*)d_in[6];
    const float* Whhb  = (const float*)d_in[7];
    const float* bb    = (const float*)d_in[8];
    const float* Wem   = (const float*)d_in[9];
    const float* bem   = (const float*)d_in[10];
    const float* trans = (const float*)d_in[11];
    float* out = (float*)d_out;

    cudaFuncSetAttribute(k_ingate, cudaFuncAttributeMaxDynamicSharedMemorySize, INGATE_SMEM);
    cudaFuncSetAttribute(k_lstm,   cudaFuncAttributeMaxDynamicSharedMemorySize, LSTM_SMEM);
    cudaFuncSetAttribute(k_emit,   cudaFuncAttributeMaxDynamicSharedMemorySize, (64*520 + 12*516)*4);

    dim3 gA(64, 8);
    k_ingate<<<gA, 256, INGATE_SMEM>>>(sent, emb, Wihf, bf, Wihb, bb);
    k_lstm<<<128, 256, LSTM_SMEM>>>(Whhf, Whhb);
    k_emit<<<L_, 768, (64*520 + 12*516)*4>>>(Wem, bem);
    k_crf<<<B_, 32>>>(tags, trans);
    k_mean<<<1, 32>>>(out);
}

// round 15
// speedup vs baseline: 1.0606x; 1.0040x over previous
#include <cuda_runtime.h>
#include <cuda_bf16.h>
#include <math.h>
#include <cstdint>

#define L_ 512
#define B_ 64
#define E_ 256
#define H_ 256
#define T_ 12
#define CS 8    // cluster size (verified working)

typedef unsigned long long u64;

// ---------------- helpers ----------------
__device__ __forceinline__ float tanhap(float x) {
    float y;
    asm("tanh.approx.f32 %0, %1;" : "=f"(y) : "f"(x));
    return y;
}
__device__ __forceinline__ float sigap(float x) {
    return fmaf(0.5f, tanhap(0.5f * x), 0.5f);
}
__device__ __forceinline__ float ex2f(float x) {
    float y;
    asm("ex2.approx.f32 %0, %1;" : "=f"(y) : "f"(x));
    return y;
}
__device__ __forceinline__ float lg2f(float x) {
    float y;
    asm("lg2.approx.f32 %0, %1;" : "=f"(y) : "f"(x));
    return y;
}
__device__ __forceinline__ uint32_t smem_u32(const void* p) {
    uint32_t a;
    asm("{ .reg .u64 t; cvta.to.shared.u64 t, %1; cvt.u32.u64 %0, t; }" : "=r"(a) : "l"(p));
    return a;
}
__device__ __forceinline__ uint32_t packbf(float lo, float hi) {
    uint32_t r;
    asm("cvt.rn.bf16x2.f32 %0, %1, %2;" : "=r"(r) : "f"(hi), "f"(lo));
    return r;
}
__device__ __forceinline__ void ldsm_x4(uint32_t& r0, uint32_t& r1, uint32_t& r2, uint32_t& r3, uint32_t addr) {
    asm volatile("ldmatrix.sync.aligned.m8n8.x4.shared.b16 {%0,%1,%2,%3}, [%4];"
        : "=r"(r0), "=r"(r1), "=r"(r2), "=r"(r3) : "r"(addr));
}
__device__ __forceinline__ void mma16816(float& d0, float& d1, float& d2, float& d3,
                                         uint32_t a0, uint32_t a1, uint32_t a2, uint32_t a3,
                                         uint32_t b0, uint32_t b1) {
    asm volatile("mma.sync.aligned.m16n8k16.row.col.f32.bf16.bf16.f32 "
        "{%0,%1,%2,%3}, {%4,%5,%6,%7}, {%8,%9}, {%0,%1,%2,%3};"
        : "+f"(d0), "+f"(d1), "+f"(d2), "+f"(d3)
        : "r"(a0), "r"(a1), "r"(a2), "r"(a3), "r"(b0), "r"(b1));
}
__device__ __forceinline__ uint32_t mapa_rank(uint32_t local, uint32_t rank) {
    uint32_t r;
    asm("mapa.shared::cluster.u32 %0, %1, %2;" : "=r"(r) : "r"(local), "r"(rank));
    return r;
}
__device__ __forceinline__ void mbar_arrive_remote(uint32_t remAddr) {
    asm volatile("mbarrier.arrive.release.cluster.shared::cluster.b64 _, [%0];"
                 :: "r"(remAddr) : "memory");
}
__device__ __forceinline__ void mbar_wait_cluster(uint32_t mbar, uint32_t parity) {
    uint32_t done = 0;
    while (!done) {
        asm volatile(
            "{\n\t.reg .pred p;\n\t"
            "mbarrier.try_wait.parity.acquire.cluster.shared::cta.b64 p, [%1], %2, 0x989680;\n\t"
            "selp.b32 %0, 1, 0, p;\n\t}"
            : "=r"(done) : "r"(mbar), "r"(parity) : "memory");
    }
}

// ---------------- scratch ----------------
__device__ float g_gx[(size_t)2*L_*1024*B_];          // input gates TRANSPOSED: [2][L][gate-row j][b]
__device__ __nv_bfloat16 g_hb[(size_t)2*L_*B_*H_];    // hidden bf16
__device__ float g_emit[(size_t)L_*B_*T_];
__device__ float g_nll[B_];

// ---------------- input-gate GEMM on HMMA (mma.sync bf16; R12-identical) ----------------
static const int IG_PITCH = 528;
static const int IG_SM_W  = 0;
static const int IG_SM_X  = 256 * IG_PITCH;
static const int IG_SM_TOK = IG_SM_X + 64 * IG_PITCH;
static const int INGATE_SMEM = IG_SM_TOK + 256;

__global__ __launch_bounds__(256, 1) void k_ingate(
    const int* __restrict__ sent, const float* __restrict__ emb,
    const float* __restrict__ Wf, const float* __restrict__ bfv,
    const float* __restrict__ Wb, const float* __restrict__ bbv)
{
    extern __shared__ __align__(1024) char smw[];
    uint32_t smb = smem_u32(smw);
    int* tok = (int*)(smw + IG_SM_TOK);
    int lg = blockIdx.x, jb = blockIdx.y;
    int dir = jb >> 2;
    int jjb = (jb & 3) * 256;
    int tid = threadIdx.x;
    int w = tid >> 5, l = tid & 31;
    const float* W  = dir ? Wb : Wf;
    const float* bv = dir ? bbv : bfv;

    {
        const float4* Wf4 = (const float4*)(W + (size_t)jjb*256);
        #pragma unroll 4
        for (int i = 0; i < 64; i++) {
            int idx = i*256 + tid;
            int r = idx >> 6, c4 = idx & 63;
            float4 v = Wf4[(size_t)r*64 + c4];
            *(uint2*)(smw + IG_SM_W + r*IG_PITCH + c4*8) =
                make_uint2(packbf(v.x, v.y), packbf(v.z, v.w));
        }
    }
    int mb = 32*w;
    int rr0 = mb + (l >> 2);
    float bias[4];
    #pragma unroll
    for (int i = 0; i < 4; i++) bias[i] = bv[jjb + rr0 + 8*i];

    uint32_t aAddr[2];
    #pragma unroll
    for (int mt = 0; mt < 2; mt++)
        aAddr[mt] = smb + IG_SM_W + (uint32_t)((mb + mt*16 + (l & 15))*IG_PITCH + (l >> 4)*16);
    uint32_t xAddr[8];
    {
        int lrow = l & 7, grp = l >> 3;
        #pragma unroll
        for (int nt = 0; nt < 8; nt++)
            xAddr[nt] = smb + IG_SM_X + (uint32_t)((nt*8 + lrow)*IG_PITCH + grp*16);
    }
    int cc2 = (l & 3)*2;

    for (int il = 0; il < 8; il++) {
        int lcur = lg*8 + il;
        __syncthreads();
        if (tid < 64) tok[tid] = sent[tid*L_ + lcur];
        __syncthreads();
        #pragma unroll 4
        for (int i = 0; i < 16; i++) {
            int idx = i*256 + tid;
            int r = idx >> 6, c4 = idx & 63;
            float4 v = ((const float4*)emb)[(size_t)tok[r]*64 + c4];
            *(uint2*)(smw + IG_SM_X + r*IG_PITCH + c4*8) =
                make_uint2(packbf(v.x, v.y), packbf(v.z, v.w));
        }
        __syncthreads();

        float acc[2][8][4];
        #pragma unroll
        for (int mt = 0; mt < 2; mt++)
            #pragma unroll
            for (int nt = 0; nt < 8; nt++)
                #pragma unroll
                for (int k = 0; k < 4; k++) acc[mt][nt][k] = 0.f;

        #pragma unroll 2
        for (int ktp = 0; ktp < 8; ktp++) {
            uint32_t af[2][2][4];
            #pragma unroll
            for (int mt = 0; mt < 2; mt++)
                #pragma unroll
                for (int kk = 0; kk < 2; kk++)
                    ldsm_x4(af[mt][kk][0], af[mt][kk][1], af[mt][kk][2], af[mt][kk][3],
                            aAddr[mt] + (ktp*2 + kk)*32);
            #pragma unroll
            for (int nt = 0; nt < 8; nt++) {
                uint32_t b0, b1, b2, b3;
                ldsm_x4(b0, b1, b2, b3, xAddr[nt] + ktp*64);
                #pragma unroll
                for (int mt = 0; mt < 2; mt++) {
                    mma16816(acc[mt][nt][0], acc[mt][nt][1], acc[mt][nt][2], acc[mt][nt][3],
                             af[mt][0][0], af[mt][0][1], af[mt][0][2], af[mt][0][3], b0, b1);
                    mma16816(acc[mt][nt][0], acc[mt][nt][1], acc[mt][nt][2], acc[mt][nt][3],
                             af[mt][1][0], af[mt][1][1], af[mt][1][2], af[mt][1][3], b2, b3);
                }
            }
        }

        float* outb = g_gx + ((size_t)(dir*L_ + lcur)*1024 + jjb)*64;
        #pragma unroll
        for (int mt = 0; mt < 2; mt++) {
            int ra = mb + mt*16 + (l >> 2);
            int rb = ra + 8;
            float ba = bias[mt*2 + 0];
            float bb2 = bias[mt*2 + 1];
            #pragma unroll
            for (int nt = 0; nt < 8; nt++) {
                *(float2*)(outb + (size_t)ra*64 + nt*8 + cc2) =
                    make_float2(acc[mt][nt][0] + ba, acc[mt][nt][1] + ba);
                *(float2*)(outb + (size_t)rb*64 + nt*8 + cc2) =
                    make_float2(acc[mt][nt][2] + bb2, acc[mt][nt][3] + bb2);
            }
        }
    }
}

// ---------------- persistent LSTM: mma.sync, L2 h-exchange, batch-eighth (R12 skeleton) ----------------
// 128 CTAs = (dir 2) x (batch-eighth 8) x (rank 8). CTA owns hids [32p,32p+32), batches [8be,8be+8).
// R15 = R12 + gx double-buffer prefetch (loads for s+1 issued after step s's Ps store).
static const int BS_PITCH_B = 528;                    // bytes per B-tile row (8 rows)
static const int SM_PS      = 8 * BS_PITCH_B;         // 4224 (B tile)
static const int PS_PITCH   = 10;
static const int SM_MBAR    = SM_PS + 128*PS_PITCH*4; // 4224 + 5120 = 9344
static const int LSTM_SMEM  = SM_MBAR + 128;

__global__ __launch_bounds__(256, 1) __cluster_dims__(CS, 1, 1)
void k_lstm(const float* __restrict__ Whf, const float* __restrict__ Whb)
{
    extern __shared__ __align__(1024) char sm[];
    float* Ps = (float*)(sm + SM_PS);
    uint32_t smb = smem_u32(sm);
    int d  = blockIdx.x >> 6;             // direction
    int be = (blockIdx.x >> 3) & 7;       // batch eighth
    uint32_t p;
    asm("mov.u32 %0, %%cluster_ctarank;" : "=r"(p));
    int hb = (int)p * 32;
    int tid = threadIdx.x;
    int w = tid >> 5, l = tid & 31;
    const float* W = d ? Whb : Whf;

    if (tid == 0) {
        asm volatile("mbarrier.init.shared.b64 [%0], %1;" :: "r"(smb + SM_MBAR),     "r"((uint32_t)CS) : "memory");
        asm volatile("mbarrier.init.shared.b64 [%0], %1;" :: "r"(smb + SM_MBAR + 8), "r"((uint32_t)CS) : "memory");
    }
    __syncthreads();
    asm volatile("barrier.cluster.arrive.aligned;" ::: "memory");
    asm volatile("barrier.cluster.wait.aligned;" ::: "memory");

    // ---- A fragments: warp w -> m-rows [16w,16w+16) ----
    int r0 = 16*w + (l >> 2), r1 = r0 + 8;
    const float* wr0 = W + (size_t)((r0 >> 5)*H_ + hb + (r0 & 31))*H_;
    const float* wr1 = W + (size_t)((r1 >> 5)*H_ + hb + (r1 & 31))*H_;
    uint32_t A0[16], A1[16], A2[16], A3[16];
    {
        int kc0 = (l & 3)*2;
        #pragma unroll
        for (int kt = 0; kt < 16; kt++) {
            int kc = kt*16 + kc0;
            A0[kt] = packbf(wr0[kc],   wr0[kc+1]);
            A1[kt] = packbf(wr1[kc],   wr1[kc+1]);
            A2[kt] = packbf(wr0[kc+8], wr0[kc+9]);
            A3[kt] = packbf(wr1[kc+8], wr1[kc+9]);
        }
    }

    // ldsm lane row base (single n-tile of 8 local batches)
    uint32_t rowB = smb + (uint32_t)((l & 7)*BS_PITCH_B + (l >> 3)*16);

    // gx accumulator-layout mapping
    int jg0 = (r0 >> 5)*256 + hb + (r0 & 31);
    int jg1 = (r1 >> 5)*256 + hb + (r1 & 31);
    int cc  = (l & 3)*2;

    // phase-B mapping: thread owns exactly one (hid hl, local batch q)
    int hl = tid & 31, q = tid >> 5;
    float cst = 0.f;

    uint32_t rem0 = 0, rem1 = 0;
    if (tid < CS) {
        rem0 = mapa_rank(smb + SM_MBAR,     (uint32_t)tid);
        rem1 = mapa_rank(smb + SM_MBAR + 8, (uint32_t)tid);
    }

    // ---- gx prefetch for step 0 ----
    float2 gx0, gx1;
    {
        int t0 = d ? (L_-1) : 0;
        const float* base = g_gx + ((size_t)(d*L_ + t0)*1024)*64 + 8*be + cc;
        gx0 = *(const float2*)(base + (size_t)jg0*64);
        gx1 = *(const float2*)(base + (size_t)jg1*64);
    }

    for (int s = 0; s < L_; s++) {
        int t = d ? (L_-1-s) : s;

        // ---- wait + stage h (bf16 copy, this batch eighth: 4 KB) ----
        if (s == 0) {
            for (int i = tid; i < SM_PS/4; i += 256) ((uint32_t*)sm)[i] = 0;
        } else {
            int sp = s - 1;
            mbar_wait_cluster(smb + SM_MBAR + (sp & 1)*8, (uint32_t)((sp >> 1) & 1));
            int tprev = d ? (t+1) : (t-1);
            const uint4* hsrc = (const uint4*)(g_hb + (((size_t)d*L_ + tprev)*B_ + 8*be)*H_);
            int b = tid >> 5, kq = tid & 31;   // 256 uint4, one per thread
            *(uint4*)(sm + b*BS_PITCH_B + kq*16) = hsrc[tid];
        }
        __syncthreads();                               // sync A

        // ---- MMA mainloop: D[128,8], warp covers 16 m x 8 n ----
        float a0 = 0.f, a1 = 0.f, a2 = 0.f, a3 = 0.f;
        #pragma unroll
        for (int ktp = 0; ktp < 8; ktp++) {
            uint32_t b0, b1, b2, b3;
            ldsm_x4(b0, b1, b2, b3, rowB + ktp*64);
            mma16816(a0, a1, a2, a3, A0[2*ktp],   A1[2*ktp],   A2[2*ktp],   A3[2*ktp],   b0, b1);
            mma16816(a0, a1, a2, a3, A0[2*ktp+1], A1[2*ktp+1], A2[2*ktp+1], A3[2*ktp+1], b2, b3);
        }

        // ---- Ps = D + gx (single store) ----
        *(float2*)(Ps + r0*PS_PITCH + cc) = make_float2(a0 + gx0.x, a1 + gx0.y);
        *(float2*)(Ps + r1*PS_PITCH + cc) = make_float2(a2 + gx1.x, a3 + gx1.y);

        // ---- prefetch gx for step s+1 (hidden under act + signal + wait + stage) ----
        if (s + 1 < L_) {
            int tn = d ? (t-1) : (t+1);
            const float* base = g_gx + ((size_t)(d*L_ + tn)*1024)*64 + 8*be + cc;
            gx0 = *(const float2*)(base + (size_t)jg0*64);
            gx1 = *(const float2*)(base + (size_t)jg1*64);
        }
        __syncthreads();                               // sync B

        // ---- phase B: activations, c update, h out (bf16) ----
        float hout;
        {
            float vi = Ps[(  0 + hl)*PS_PITCH + q];
            float vf = Ps[( 32 + hl)*PS_PITCH + q];
            float vg = Ps[( 64 + hl)*PS_PITCH + q];
            float vo = Ps[( 96 + hl)*PS_PITCH + q];
            float ig = sigap(vi), fg = sigap(vf), gg = tanhap(vg), og = sigap(vo);
            cst = fg*cst + ig*gg;
            hout = og * tanhap(cst);
        }
        g_hb[(((size_t)d*L_ + t)*B_ + 8*be + q)*H_ + hb + hl] = __float2bfloat16(hout);
        __syncthreads();                               // sync C (R12 structure restored)
        if (tid < CS && s < L_-1) {
            mbar_arrive_remote((s & 1) ? rem1 : rem0);
        }
    }
}

// ---------------- emission GEMM (reads bf16 h; unchanged) ----------------
__global__ __launch_bounds__(768) void k_emit(const float* __restrict__ Wem,
                                              const float* __restrict__ bem)
{
    extern __shared__ float smc[];
    float* Hcat = smc;            // [64][520]
    float* Wsm  = smc + 64*520;   // [12][516]
    int l   = blockIdx.x;
    int tid = threadIdx.x;
    const uint4* hf  = (const uint4*)(g_hb + ((size_t)0*L_ + l)*B_*H_);
    const uint4* hbk = (const uint4*)(g_hb + ((size_t)1*L_ + l)*B_*H_);
    for (int e = tid; e < 2048; e += 768) {
        int r = e >> 5, kq = e & 31;
        uint4 vf = hf[e], vb = hbk[e];
        const __nv_bfloat162* pf = (const __nv_bfloat162*)&vf;
        const __nv_bfloat162* pb = (const __nv_bfloat162*)&vb;
        float* df = Hcat + r*520 + kq*8;
        float* db = Hcat + r*520 + 256 + kq*8;
        #pragma unroll
        for (int qq = 0; qq < 4; qq++) {
            float2 f2 = __bfloat1622float2(pf[qq]);
            float2 b2 = __bfloat1622float2(pb[qq]);
            df[2*qq] = f2.x; df[2*qq+1] = f2.y;
            db[2*qq] = b2.x; db[2*qq+1] = b2.y;
        }
    }
    for (int e = tid; e < 12*512; e += 768)
        Wsm[(e >> 9)*516 + (e & 511)] = Wem[e];
    __syncthreads();

    int b = tid / 12, tg = tid - b*12;
    float acc = bem[tg];
    const float4* hrow = (const float4*)(Hcat + b*520);
    const float4* wrow = (const float4*)(Wsm + tg*516);
    #pragma unroll 8
    for (int k4 = 0; k4 < 128; k4++) {
        float4 x = hrow[k4]; float4 w = wrow[k4];
        acc += w.x*x.x + w.y*x.y + w.z*x.z + w.w*x.w;
    }
    g_emit[((size_t)l*B_ + b)*T_ + tg] = acc;
}

// ---------------- CRF NLL: emissions staged in smem, base-2 scan (unchanged) ----------------
__global__ void k_crf(const int* __restrict__ tags, const float* __restrict__ trans)
{
    __shared__ float se[512*12];
    __shared__ float tr[T_*T_];
    int b = blockIdx.x;
    int lane = threadIdx.x;
    for (int i = lane; i < T_*T_; i += 32) tr[i] = trans[i];
    {
        const float4* src = (const float4*)g_emit;
        float4* dst = (float4*)se;
        for (int i = lane; i < 1536; i += 32) {
            int l = i / 3, j = i - 3*l;
            dst[i] = src[((size_t)l*64 + b)*3 + j];
        }
    }
    __syncwarp();

    const unsigned FULL = 0xffffffffu;
    const float I2 = 1.4426950408889634f;
    const float LN2 = 0.6931471805599453f;
    int mylane = (lane < T_) ? lane : 0;
    float trr2[T_];
    #pragma unroll
    for (int t2 = 0; t2 < T_; t2++) trr2[t2] = tr[t2*T_ + mylane] * I2;

    float a2 = se[mylane] * I2;
    #pragma unroll 4
    for (int l = 1; l < L_; l++) {
        float e2 = se[l*12 + mylane] * I2;
        float v[T_];
        #pragma unroll
        for (int t2 = 0; t2 < T_; t2++)
            v[t2] = __shfl_sync(FULL, a2, t2) + trr2[t2];
        float ex[T_];
        ex[0] = 1.0f;
        #pragma unroll
        for (int t2 = 1; t2 < T_; t2++) ex[t2] = ex2f(v[t2] - v[0]);
        float s01 = ex[0] + ex[1],  s23 = ex[2] + ex[3];
        float s45 = ex[4] + ex[5],  s67 = ex[6] + ex[7];
        float s89 = ex[8] + ex[9],  sAB = ex[10] + ex[11];
        float ssum = ((s01 + s23) + (s45 + s67)) + (s89 + sAB);
        a2 = v[0] + lg2f(ssum) + e2;
    }
    float am = (lane < T_) ? a2 : -1e30f;
    float mm = am;
    for (int o = 16; o; o >>= 1) mm = fmaxf(mm, __shfl_xor_sync(FULL, mm, o));
    float es = (lane < T_) ? ex2f(a2 - mm) : 0.f;
    for (int o = 16; o; o >>= 1) es += __shfl_xor_sync(FULL, es, o);
    float logZ = (mm + lg2f(es)) * LN2;

    float eg = 0.f, tg2 = 0.f;
    for (int l = lane; l < L_; l += 32) {
        int tv = tags[b*L_ + l];
        eg += se[l*12 + tv];
    }
    for (int l = lane; l < L_-1; l += 32) {
        int t0v = tags[b*L_ + l], t1v = tags[b*L_ + l + 1];
        tg2 += tr[t0v*T_ + t1v];
    }
    for (int o = 16; o; o >>= 1) {
        eg  += __shfl_xor_sync(FULL, eg,  o);
        tg2 += __shfl_xor_sync(FULL, tg2, o);
    }
    if (lane == 0) g_nll[b] = logZ - eg - tg2;
}

__global__ void k_mean(float* out)
{
    int lane = threadIdx.x;
    float s = (lane < 32) ? g_nll[lane] + g_nll[lane + 32] : 0.f;
    s += __shfl_xor_sync(0xffffffffu, s, 16);
    s += __shfl_xor_sync(0xffffffffu, s, 8);
    s += __shfl_xor_sync(0xffffffffu, s, 4);
    s += __shfl_xor_sync(0xffffffffu, s, 2);
    s += __shfl_xor_sync(0xffffffffu, s, 1);
    if (lane == 0) out[0] = s / (float)B_;
}

// ---------------- launch ----------------
extern "C" void kernel_launch(void* const* d_in, const int* in_sizes, int n_in,
                              void* d_out, int out_size)
{
    const int*   sent  = (const int*)  d_in[0];
    const int*   tags  = (const int*)  d_in[1];
    const float* emb   = (const float*)d_in[2];
    const float* Wihf  = (const float*)d_in[3];
    const float* Whhf  = (const float*)d_in[4];
    const float* bf    = (const float*)d_in[5];
    const float* Wihb  = (const float*)d_in[6];
    const float* Whhb  = (const float*)d_in[7];
    const float* bb    = (const float*)d_in[8];
    const float* Wem   = (const float*)d_in[9];
    const float* bem   = (const float*)d_in[10];
    const float* trans = (const float*)d_in[11];
    float* out = (float*)d_out;

    cudaFuncSetAttribute(k_ingate, cudaFuncAttributeMaxDynamicSharedMemorySize, INGATE_SMEM);
    cudaFuncSetAttribute(k_lstm,   cudaFuncAttributeMaxDynamicSharedMemorySize, LSTM_SMEM);
    cudaFuncSetAttribute(k_emit,   cudaFuncAttributeMaxDynamicSharedMemorySize, (64*520 + 12*516)*4);

    dim3 gA(64, 8);
    k_ingate<<<gA, 256, INGATE_SMEM>>>(sent, emb, Wihf, bf, Wihb, bb);
    k_lstm<<<128, 256, LSTM_SMEM>>>(Whhf, Whhb);
    k_emit<<<L_, 768, (64*520 + 12*516)*4>>>(Wem, bem);
    k_crf<<<B_, 32>>>(tags, trans);
    k_mean<<<1, 32>>>(out);
}

// round 16
// speedup vs baseline: 1.2099x; 1.1407x over previous
#include <cuda_runtime.h>
#include <cuda_bf16.h>
#include <math.h>
#include <cstdint>

#define L_ 512
#define B_ 64
#define E_ 256
#define H_ 256
#define T_ 12
#define CS 8    // cluster size (verified working)

typedef unsigned long long u64;

// ---------------- helpers ----------------
__device__ __forceinline__ float tanhap(float x) {
    float y;
    asm("tanh.approx.f32 %0, %1;" : "=f"(y) : "f"(x));
    return y;
}
__device__ __forceinline__ float sigap(float x) {
    return fmaf(0.5f, tanhap(0.5f * x), 0.5f);
}
__device__ __forceinline__ float ex2f(float x) {
    float y;
    asm("ex2.approx.f32 %0, %1;" : "=f"(y) : "f"(x));
    return y;
}
__device__ __forceinline__ float lg2f(float x) {
    float y;
    asm("lg2.approx.f32 %0, %1;" : "=f"(y) : "f"(x));
    return y;
}
__device__ __forceinline__ uint32_t smem_u32(const void* p) {
    uint32_t a;
    asm("{ .reg .u64 t; cvta.to.shared.u64 t, %1; cvt.u32.u64 %0, t; }" : "=r"(a) : "l"(p));
    return a;
}
__device__ __forceinline__ uint32_t packbf(float lo, float hi) {
    uint32_t r;
    asm("cvt.rn.bf16x2.f32 %0, %1, %2;" : "=r"(r) : "f"(hi), "f"(lo));
    return r;
}
__device__ __forceinline__ void ldsm_x4(uint32_t& r0, uint32_t& r1, uint32_t& r2, uint32_t& r3, uint32_t addr) {
    asm volatile("ldmatrix.sync.aligned.m8n8.x4.shared.b16 {%0,%1,%2,%3}, [%4];"
        : "=r"(r0), "=r"(r1), "=r"(r2), "=r"(r3) : "r"(addr));
}
__device__ __forceinline__ void mma16816(float& d0, float& d1, float& d2, float& d3,
                                         uint32_t a0, uint32_t a1, uint32_t a2, uint32_t a3,
                                         uint32_t b0, uint32_t b1) {
    asm volatile("mma.sync.aligned.m16n8k16.row.col.f32.bf16.bf16.f32 "
        "{%0,%1,%2,%3}, {%4,%5,%6,%7}, {%8,%9}, {%0,%1,%2,%3};"
        : "+f"(d0), "+f"(d1), "+f"(d2), "+f"(d3)
        : "r"(a0), "r"(a1), "r"(a2), "r"(a3), "r"(b0), "r"(b1));
}
__device__ __forceinline__ uint32_t mapa_rank(uint32_t local, uint32_t rank) {
    uint32_t r;
    asm("mapa.shared::cluster.u32 %0, %1, %2;" : "=r"(r) : "r"(local), "r"(rank));
    return r;
}
__device__ __forceinline__ void mbar_arrive_remote(uint32_t remAddr) {
    asm volatile("mbarrier.arrive.release.cluster.shared::cluster.b64 _, [%0];"
                 :: "r"(remAddr) : "memory");
}
__device__ __forceinline__ void mbar_wait_cluster(uint32_t mbar, uint32_t parity) {
    uint32_t done = 0;
    while (!done) {
        asm volatile(
            "{\n\t.reg .pred p;\n\t"
            "mbarrier.try_wait.parity.acquire.cluster.shared::cta.b64 p, [%1], %2, 0x989680;\n\t"
            "selp.b32 %0, 1, 0, p;\n\t}"
            : "=r"(done) : "r"(mbar), "r"(parity) : "memory");
    }
}

// ---------------- scratch ----------------
__device__ float g_gx[(size_t)2*L_*1024*B_];          // input gates TRANSPOSED: [2][L][gate-row j][b]
__device__ __nv_bfloat16 g_hb[(size_t)2*L_*B_*H_];    // hidden bf16
__device__ float g_emit[(size_t)L_*B_*T_];
__device__ float g_nll[B_];
__device__ int   g_done;                               // crf completion counter (self-resetting)

// ---------------- input-gate GEMM on HMMA (16 timesteps per CTA) ----------------
static const int IG_PITCH = 528;
static const int IG_SM_W  = 0;
static const int IG_SM_X  = 256 * IG_PITCH;
static const int IG_SM_TOK = IG_SM_X + 64 * IG_PITCH;
static const int INGATE_SMEM = IG_SM_TOK + 256;

__global__ __launch_bounds__(256, 1) void k_ingate(
    const int* __restrict__ sent, const float* __restrict__ emb,
    const float* __restrict__ Wf, const float* __restrict__ bfv,
    const float* __restrict__ Wb, const float* __restrict__ bbv)
{
    extern __shared__ __align__(1024) char smw[];
    uint32_t smb = smem_u32(smw);
    int* tok = (int*)(smw + IG_SM_TOK);
    int lg = blockIdx.x, jb = blockIdx.y;
    int dir = jb >> 2;
    int jjb = (jb & 3) * 256;
    int tid = threadIdx.x;
    int w = tid >> 5, l = tid & 31;
    const float* W  = dir ? Wb : Wf;
    const float* bv = dir ? bbv : bfv;

    {
        const float4* Wf4 = (const float4*)(W + (size_t)jjb*256);
        #pragma unroll 4
        for (int i = 0; i < 64; i++) {
            int idx = i*256 + tid;
            int r = idx >> 6, c4 = idx & 63;
            float4 v = Wf4[(size_t)r*64 + c4];
            *(uint2*)(smw + IG_SM_W + r*IG_PITCH + c4*8) =
                make_uint2(packbf(v.x, v.y), packbf(v.z, v.w));
        }
    }
    int mb = 32*w;
    int rr0 = mb + (l >> 2);
    float bias[4];
    #pragma unroll
    for (int i = 0; i < 4; i++) bias[i] = bv[jjb + rr0 + 8*i];

    uint32_t aAddr[2];
    #pragma unroll
    for (int mt = 0; mt < 2; mt++)
        aAddr[mt] = smb + IG_SM_W + (uint32_t)((mb + mt*16 + (l & 15))*IG_PITCH + (l >> 4)*16);
    uint32_t xAddr[8];
    {
        int lrow = l & 7, grp = l >> 3;
        #pragma unroll
        for (int nt = 0; nt < 8; nt++)
            xAddr[nt] = smb + IG_SM_X + (uint32_t)((nt*8 + lrow)*IG_PITCH + grp*16);
    }
    int cc2 = (l & 3)*2;

    for (int il = 0; il < 16; il++) {
        int lcur = lg*16 + il;
        __syncthreads();
        if (tid < 64) tok[tid] = sent[tid*L_ + lcur];
        __syncthreads();
        #pragma unroll 4
        for (int i = 0; i < 16; i++) {
            int idx = i*256 + tid;
            int r = idx >> 6, c4 = idx & 63;
            float4 v = ((const float4*)emb)[(size_t)tok[r]*64 + c4];
            *(uint2*)(smw + IG_SM_X + r*IG_PITCH + c4*8) =
                make_uint2(packbf(v.x, v.y), packbf(v.z, v.w));
        }
        __syncthreads();

        float acc[2][8][4];
        #pragma unroll
        for (int mt = 0; mt < 2; mt++)
            #pragma unroll
            for (int nt = 0; nt < 8; nt++)
                #pragma unroll
                for (int k = 0; k < 4; k++) acc[mt][nt][k] = 0.f;

        #pragma unroll 2
        for (int ktp = 0; ktp < 8; ktp++) {
            uint32_t af[2][2][4];
            #pragma unroll
            for (int mt = 0; mt < 2; mt++)
                #pragma unroll
                for (int kk = 0; kk < 2; kk++)
                    ldsm_x4(af[mt][kk][0], af[mt][kk][1], af[mt][kk][2], af[mt][kk][3],
                            aAddr[mt] + (ktp*2 + kk)*32);
            #pragma unroll
            for (int nt = 0; nt < 8; nt++) {
                uint32_t b0, b1, b2, b3;
                ldsm_x4(b0, b1, b2, b3, xAddr[nt] + ktp*64);
                #pragma unroll
                for (int mt = 0; mt < 2; mt++) {
                    mma16816(acc[mt][nt][0], acc[mt][nt][1], acc[mt][nt][2], acc[mt][nt][3],
                             af[mt][0][0], af[mt][0][1], af[mt][0][2], af[mt][0][3], b0, b1);
                    mma16816(acc[mt][nt][0], acc[mt][nt][1], acc[mt][nt][2], acc[mt][nt][3],
                             af[mt][1][0], af[mt][1][1], af[mt][1][2], af[mt][1][3], b2, b3);
                }
            }
        }

        float* outb = g_gx + ((size_t)(dir*L_ + lcur)*1024 + jjb)*64;
        #pragma unroll
        for (int mt = 0; mt < 2; mt++) {
            int ra = mb + mt*16 + (l >> 2);
            int rb = ra + 8;
            float ba = bias[mt*2 + 0];
            float bb2 = bias[mt*2 + 1];
            #pragma unroll
            for (int nt = 0; nt < 8; nt++) {
                *(float2*)(outb + (size_t)ra*64 + nt*8 + cc2) =
                    make_float2(acc[mt][nt][0] + ba, acc[mt][nt][1] + ba);
                *(float2*)(outb + (size_t)rb*64 + nt*8 + cc2) =
                    make_float2(acc[mt][nt][2] + bb2, acc[mt][nt][3] + bb2);
            }
        }
    }
}

// ---------------- persistent LSTM: R12 byte-identical ----------------
static const int BS_PITCH_B = 528;                    // bytes per B-tile row (8 rows)
static const int SM_PS      = 8 * BS_PITCH_B;         // 4224 (B tile)
static const int PS_PITCH   = 10;
static const int SM_MBAR    = SM_PS + 128*PS_PITCH*4; // 4224 + 5120 = 9344
static const int LSTM_SMEM  = SM_MBAR + 128;

__global__ __launch_bounds__(256, 1) __cluster_dims__(CS, 1, 1)
void k_lstm(const float* __restrict__ Whf, const float* __restrict__ Whb)
{
    extern __shared__ __align__(1024) char sm[];
    float* Ps = (float*)(sm + SM_PS);
    uint32_t smb = smem_u32(sm);
    int d  = blockIdx.x >> 6;             // direction
    int be = (blockIdx.x >> 3) & 7;       // batch eighth
    uint32_t p;
    asm("mov.u32 %0, %%cluster_ctarank;" : "=r"(p));
    int hb = (int)p * 32;
    int tid = threadIdx.x;
    int w = tid >> 5, l = tid & 31;
    const float* W = d ? Whb : Whf;

    if (tid == 0) {
        asm volatile("mbarrier.init.shared.b64 [%0], %1;" :: "r"(smb + SM_MBAR),     "r"((uint32_t)CS) : "memory");
        asm volatile("mbarrier.init.shared.b64 [%0], %1;" :: "r"(smb + SM_MBAR + 8), "r"((uint32_t)CS) : "memory");
    }
    __syncthreads();
    asm volatile("barrier.cluster.arrive.aligned;" ::: "memory");
    asm volatile("barrier.cluster.wait.aligned;" ::: "memory");

    // ---- A fragments: warp w -> m-rows [16w,16w+16) ----
    int r0 = 16*w + (l >> 2), r1 = r0 + 8;
    const float* wr0 = W + (size_t)((r0 >> 5)*H_ + hb + (r0 & 31))*H_;
    const float* wr1 = W + (size_t)((r1 >> 5)*H_ + hb + (r1 & 31))*H_;
    uint32_t A0[16], A1[16], A2[16], A3[16];
    {
        int kc0 = (l & 3)*2;
        #pragma unroll
        for (int kt = 0; kt < 16; kt++) {
            int kc = kt*16 + kc0;
            A0[kt] = packbf(wr0[kc],   wr0[kc+1]);
            A1[kt] = packbf(wr1[kc],   wr1[kc+1]);
            A2[kt] = packbf(wr0[kc+8], wr0[kc+9]);
            A3[kt] = packbf(wr1[kc+8], wr1[kc+9]);
        }
    }

    // ldsm lane row base (single n-tile of 8 local batches)
    uint32_t rowB = smb + (uint32_t)((l & 7)*BS_PITCH_B + (l >> 3)*16);

    // gx accumulator-layout mapping
    int jg0 = (r0 >> 5)*256 + hb + (r0 & 31);
    int jg1 = (r1 >> 5)*256 + hb + (r1 & 31);
    int cc  = (l & 3)*2;

    // phase-B mapping: thread owns exactly one (hid hl, local batch q)
    int hl = tid & 31, q = tid >> 5;
    float cst = 0.f;

    uint32_t rem0 = 0, rem1 = 0;
    if (tid < CS) {
        rem0 = mapa_rank(smb + SM_MBAR,     (uint32_t)tid);
        rem1 = mapa_rank(smb + SM_MBAR + 8, (uint32_t)tid);
    }

    for (int s = 0; s < L_; s++) {
        int t = d ? (L_-1-s) : s;

        // ---- gx prefetch (independent of h) ----
        float2 gx0, gx1;
        {
            const float* base = g_gx + ((size_t)(d*L_ + t)*1024)*64 + 8*be + cc;
            gx0 = *(const float2*)(base + (size_t)jg0*64);
            gx1 = *(const float2*)(base + (size_t)jg1*64);
        }

        // ---- wait + stage h (bf16 copy, this batch eighth: 4 KB) ----
        if (s == 0) {
            for (int i = tid; i < SM_PS/4; i += 256) ((uint32_t*)sm)[i] = 0;
        } else {
            int sp = s - 1;
            mbar_wait_cluster(smb + SM_MBAR + (sp & 1)*8, (uint32_t)((sp >> 1) & 1));
            int tprev = d ? (t+1) : (t-1);
            const uint4* hsrc = (const uint4*)(g_hb + (((size_t)d*L_ + tprev)*B_ + 8*be)*H_);
            int b = tid >> 5, kq = tid & 31;   // 256 uint4, one per thread
            *(uint4*)(sm + b*BS_PITCH_B + kq*16) = hsrc[tid];
        }
        __syncthreads();

        // ---- MMA mainloop: D[128,8], warp covers 16 m x 8 n ----
        float a0 = 0.f, a1 = 0.f, a2 = 0.f, a3 = 0.f;
        #pragma unroll
        for (int ktp = 0; ktp < 8; ktp++) {
            uint32_t b0, b1, b2, b3;
            ldsm_x4(b0, b1, b2, b3, rowB + ktp*64);
            mma16816(a0, a1, a2, a3, A0[2*ktp],   A1[2*ktp],   A2[2*ktp],   A3[2*ktp],   b0, b1);
            mma16816(a0, a1, a2, a3, A0[2*ktp+1], A1[2*ktp+1], A2[2*ktp+1], A3[2*ktp+1], b2, b3);
        }

        // ---- Ps = D + gx (single store) ----
        *(float2*)(Ps + r0*PS_PITCH + cc) = make_float2(a0 + gx0.x, a1 + gx0.y);
        *(float2*)(Ps + r1*PS_PITCH + cc) = make_float2(a2 + gx1.x, a3 + gx1.y);
        __syncthreads();

        // ---- phase B: activations, c update, h out (bf16) ----
        float hout;
        {
            float vi = Ps[(  0 + hl)*PS_PITCH + q];
            float vf = Ps[( 32 + hl)*PS_PITCH + q];
            float vg = Ps[( 64 + hl)*PS_PITCH + q];
            float vo = Ps[( 96 + hl)*PS_PITCH + q];
            float ig = sigap(vi), fg = sigap(vf), gg = tanhap(vg), og = sigap(vo);
            cst = fg*cst + ig*gg;
            hout = og * tanhap(cst);
        }
        g_hb[(((size_t)d*L_ + t)*B_ + 8*be + q)*H_ + hb + hl] = __float2bfloat16(hout);
        __syncthreads();
        if (tid < CS && s < L_-1) {
            mbar_arrive_remote((s & 1) ? rem1 : rem0);
        }
    }
}

// ---------------- emission GEMM: bf16 Hcat (pure-copy staging, 2 CTAs/SM) ----------------
static const int EM_ROW4 = 66;                         // uint4 per Hcat row (64 data + 2 pad)
static const int EM_HC_BYTES = 64 * EM_ROW4 * 16;      // 67584
static const int EMIT_SMEM = EM_HC_BYTES + 12*516*4;   // + Wsm fp32 = 92352

__global__ __launch_bounds__(768, 2) void k_emit(const float* __restrict__ Wem,
                                                 const float* __restrict__ bem)
{
    extern __shared__ __align__(16) char smc[];
    uint4* Hc4 = (uint4*)smc;
    float* Wsm = (float*)(smc + EM_HC_BYTES);
    int l   = blockIdx.x;
    int tid = threadIdx.x;
    const uint4* hf  = (const uint4*)(g_hb + ((size_t)0*L_ + l)*B_*H_);
    const uint4* hbk = (const uint4*)(g_hb + ((size_t)1*L_ + l)*B_*H_);
    for (int e = tid; e < 2048; e += 768) {
        int r = e >> 5, kq = e & 31;
        Hc4[r*EM_ROW4 + kq]      = hf[e];
        Hc4[r*EM_ROW4 + 32 + kq] = hbk[e];
    }
    for (int e = tid; e < 12*512; e += 768)
        Wsm[(e >> 9)*516 + (e & 511)] = Wem[e];
    __syncthreads();

    int b = tid / 12, tg = tid - b*12;
    float acc = bem[tg];
    const uint2* hrow = (const uint2*)(Hc4 + b*EM_ROW4);   // 128 uint2 (4 halves each)
    const float4* wrow = (const float4*)(Wsm + tg*516);
    #pragma unroll 8
    for (int k4 = 0; k4 < 128; k4++) {
        uint2 hv = hrow[k4];
        float2 f01 = __bfloat1622float2(*(const __nv_bfloat162*)&hv.x);
        float2 f23 = __bfloat1622float2(*(const __nv_bfloat162*)&hv.y);
        float4 wv = wrow[k4];
        acc += wv.x*f01.x + wv.y*f01.y + wv.z*f23.x + wv.w*f23.y;
    }
    g_emit[((size_t)l*B_ + b)*T_ + tg] = acc;
}

// ---------------- CRF NLL + fused mean (last CTA reduces) ----------------
__global__ void k_crf(const int* __restrict__ tags, const float* __restrict__ trans,
                      float* __restrict__ out)
{
    __shared__ float se[512*12];
    __shared__ float tr[T_*T_];
    int b = blockIdx.x;
    int lane = threadIdx.x;
    for (int i = lane; i < T_*T_; i += 32) tr[i] = trans[i];
    {
        const float4* src = (const float4*)g_emit;
        float4* dst = (float4*)se;
        for (int i = lane; i < 1536; i += 32) {
            int l = i / 3, j = i - 3*l;
            dst[i] = src[((size_t)l*64 + b)*3 + j];
        }
    }
    __syncwarp();

    const unsigned FULL = 0xffffffffu;
    const float I2 = 1.4426950408889634f;
    const float LN2 = 0.6931471805599453f;
    int mylane = (lane < T_) ? lane : 0;
    float trr2[T_];
    #pragma unroll
    for (int t2 = 0; t2 < T_; t2++) trr2[t2] = tr[t2*T_ + mylane] * I2;

    float a2 = se[mylane] * I2;
    #pragma unroll 4
    for (int l = 1; l < L_; l++) {
        float e2 = se[l*12 + mylane] * I2;
        float v[T_];
        #pragma unroll
        for (int t2 = 0; t2 < T_; t2++)
            v[t2] = __shfl_sync(FULL, a2, t2) + trr2[t2];
        float ex[T_];
        ex[0] = 1.0f;
        #pragma unroll
        for (int t2 = 1; t2 < T_; t2++) ex[t2] = ex2f(v[t2] - v[0]);
        float s01 = ex[0] + ex[1],  s23 = ex[2] + ex[3];
        float s45 = ex[4] + ex[5],  s67 = ex[6] + ex[7];
        float s89 = ex[8] + ex[9],  sAB = ex[10] + ex[11];
        float ssum = ((s01 + s23) + (s45 + s67)) + (s89 + sAB);
        a2 = v[0] + lg2f(ssum) + e2;
    }
    float am = (lane < T_) ? a2 : -1e30f;
    float mm = am;
    for (int o = 16; o; o >>= 1) mm = fmaxf(mm, __shfl_xor_sync(FULL, mm, o));
    float es = (lane < T_) ? ex2f(a2 - mm) : 0.f;
    for (int o = 16; o; o >>= 1) es += __shfl_xor_sync(FULL, es, o);
    float logZ = (mm + lg2f(es)) * LN2;

    float eg = 0.f, tg2 = 0.f;
    for (int l = lane; l < L_; l += 32) {
        int tv = tags[b*L_ + l];
        eg += se[l*12 + tv];
    }
    for (int l = lane; l < L_-1; l += 32) {
        int t0v = tags[b*L_ + l], t1v = tags[b*L_ + l + 1];
        tg2 += tr[t0v*T_ + t1v];
    }
    for (int o = 16; o; o >>= 1) {
        eg  += __shfl_xor_sync(FULL, eg,  o);
        tg2 += __shfl_xor_sync(FULL, tg2, o);
    }
    if (lane == 0) g_nll[b] = logZ - eg - tg2;

    // fused mean: last finishing CTA reduces all 64 NLLs
    __shared__ int s_rank;
    if (lane == 0) {
        __threadfence();
        s_rank = atomicAdd(&g_done, 1);
    }
    __syncwarp();
    if (__shfl_sync(FULL, s_rank, 0) == B_ - 1) {
        __threadfence();
        float s = g_nll[lane] + g_nll[lane + 32];
        for (int o = 16; o; o >>= 1) s += __shfl_xor_sync(FULL, s, o);
        if (lane == 0) {
            out[0] = s / (float)B_;
            g_done = 0;                       // reset for next graph replay
        }
    }
}

// ---------------- launch ----------------
extern "C" void kernel_launch(void* const* d_in, const int* in_sizes, int n_in,
                              void* d_out, int out_size)
{
    const int*   sent  = (const int*)  d_in[0];
    const int*   tags  = (const int*)  d_in[1];
    const float* emb   = (const float*)d_in[2];
    const float* Wihf  = (const float*)d_in[3];
    const float* Whhf  = (const float*)d_in[4];
    const float* bf    = (const float*)d_in[5];
    const float* Wihb  = (const float*)d_in[6];
    const float* Whhb  = (const float*)d_in[7];
    const float* bb    = (const float*)d_in[8];
    const float* Wem   = (const float*)d_in[9];
    const float* bem   = (const float*)d_in[10];
    const float* trans = (const float*)d_in[11];
    float* out = (float*)d_out;

    cudaFuncSetAttribute(k_ingate, cudaFuncAttributeMaxDynamicSharedMemorySize, INGATE_SMEM);
    cudaFuncSetAttribute(k_lstm,   cudaFuncAttributeMaxDynamicSharedMemorySize, LSTM_SMEM);
    cudaFuncSetAttribute(k_emit,   cudaFuncAttributeMaxDynamicSharedMemorySize, EMIT_SMEM);

    dim3 gA(32, 8);
    k_ingate<<<gA, 256, INGATE_SMEM>>>(sent, emb, Wihf, bf, Wihb, bb);
    k_lstm<<<128, 256, LSTM_SMEM>>>(Whhf, Whhb);
    k_emit<<<L_, 768, EMIT_SMEM>>>(Wem, bem);
    k_crf<<<B_, 32>>>(tags, trans, out);
}